// round 5
// baseline (speedup 1.0000x reference)
#include <cuda_runtime.h>
#include <cstdint>

// ---------------------------------------------------------------------------
// out = relu(x - x@P + z@P) with P = c c^T (rank-1, ||c|| = 1).
// c is reconstructed from one row of P: c = P[k,:] * rsqrt(P[k,k]).
// Three streaming kernels, all barrier-light:
//   prep  : pivot + build c + z.c            (~1.5us)
//   dot   : alpha[b] = z.c - x_b.c           (warp-per-row, no barriers)
//   apply : out = relu(x + alpha*c)          (block-per-row, no barriers;
//                                             x is L2-resident from dot pass)
// ---------------------------------------------------------------------------

#define MAX_D 8192
#define MAX_B 8192

__device__ float g_c[MAX_D];      // reconstructed CAV direction
__device__ float g_zc;            // z . c
__device__ float g_alpha[MAX_B];  // per-row correction coefficient

// ---------------- prep: one block, 1024 threads ----------------------------
// Pivot = argmax of P[i,i] over i < min(D,1024) (1 strided load per thread —
// any non-tiny pivot reconstructs c exactly up to fp32 rounding).
__global__ void __launch_bounds__(1024, 1)
prep_kernel(const float* __restrict__ P, const float* __restrict__ z, int D) {
    __shared__ float svals[1024];
    __shared__ int   sidx[1024];
    const int t = threadIdx.x;

    const int nscan = (D < 1024) ? D : 1024;
    float v = (t < nscan) ? P[(size_t)t * D + t] : -3.0e38f;
    svals[t] = v;
    sidx[t]  = t;
    __syncthreads();
    #pragma unroll
    for (int s = 512; s > 0; s >>= 1) {
        if (t < s && svals[t + s] > svals[t]) {
            svals[t] = svals[t + s];
            sidx[t]  = sidx[t + s];
        }
        __syncthreads();
    }
    const int   k   = sidx[0];
    const float inv = rsqrtf(svals[0]);
    __syncthreads();   // done reading svals/sidx before reuse

    // build c from row k (contiguous -> float4) and accumulate z.c
    const float4* __restrict__ row = reinterpret_cast<const float4*>(P + (size_t)k * D);
    const float4* __restrict__ z4  = reinterpret_cast<const float4*>(z);
    float4* __restrict__ c4        = reinterpret_cast<float4*>(g_c);
    const int n4 = D >> 2;

    float part = 0.0f;
    for (int j = t; j < n4; j += 1024) {
        float4 r = row[j], zz = z4[j];
        float4 c;
        c.x = r.x * inv; c.y = r.y * inv; c.z = r.z * inv; c.w = r.w * inv;
        c4[j] = c;
        part = fmaf(zz.x, c.x, part);
        part = fmaf(zz.y, c.y, part);
        part = fmaf(zz.z, c.z, part);
        part = fmaf(zz.w, c.w, part);
    }
    svals[t] = part;
    __syncthreads();
    #pragma unroll
    for (int s = 512; s > 0; s >>= 1) {
        if (t < s) svals[t] += svals[t + s];
        __syncthreads();
    }
    if (t == 0) g_zc = svals[0];
}

// ---------------- dot: warp-per-row, zero block barriers --------------------
__global__ void __launch_bounds__(128, 8)
dot_kernel(const float* __restrict__ x, int D, int B) {
    const int w = blockIdx.x * (blockDim.x >> 5) + (threadIdx.x >> 5);
    if (w >= B) return;
    const int lane = threadIdx.x & 31;

    const float4* __restrict__ xr = reinterpret_cast<const float4*>(x + (size_t)w * D);
    const float4* __restrict__ cr = reinterpret_cast<const float4*>(g_c);
    const int n4 = D >> 2;

    float p0 = 0.f, p1 = 0.f, p2 = 0.f, p3 = 0.f;
    #pragma unroll 8
    for (int j = lane; j < n4; j += 32) {
        float4 a = xr[j];
        float4 c = cr[j];
        p0 = fmaf(a.x, c.x, p0);
        p1 = fmaf(a.y, c.y, p1);
        p2 = fmaf(a.z, c.z, p2);
        p3 = fmaf(a.w, c.w, p3);
    }
    float part = (p0 + p1) + (p2 + p3);
    #pragma unroll
    for (int o = 16; o > 0; o >>= 1)
        part += __shfl_xor_sync(0xffffffffu, part, o);
    if (lane == 0) g_alpha[w] = g_zc - part;
}

// ---------------- apply: block-per-row, pure streaming ----------------------
__global__ void __launch_bounds__(256, 8)
apply_kernel(const float* __restrict__ x, float* __restrict__ out, int D) {
    const size_t row_off = (size_t)blockIdx.x * (size_t)D;
    const float alpha = g_alpha[blockIdx.x];

    const float4* __restrict__ xr = reinterpret_cast<const float4*>(x + row_off);
    const float4* __restrict__ cr = reinterpret_cast<const float4*>(g_c);
    float4* __restrict__ orow     = reinterpret_cast<float4*>(out + row_off);
    const int n4 = D >> 2;

    #pragma unroll 4
    for (int j = threadIdx.x; j < n4; j += 256) {
        float4 a = xr[j];
        float4 c = cr[j];
        float4 o;
        o.x = fmaxf(fmaf(alpha, c.x, a.x), 0.0f);
        o.y = fmaxf(fmaf(alpha, c.y, a.y), 0.0f);
        o.z = fmaxf(fmaf(alpha, c.z, a.z), 0.0f);
        o.w = fmaxf(fmaf(alpha, c.w, a.w), 0.0f);
        orow[j] = o;
    }
}

extern "C" void kernel_launch(void* const* d_in, const int* in_sizes, int n_in,
                              void* d_out, int out_size) {
    // Identify inputs by element count: z = smallest (D), projection = D*D, x = B*D
    int zi = 0;
    for (int i = 1; i < n_in; i++)
        if (in_sizes[i] < in_sizes[zi]) zi = i;
    const int D = in_sizes[zi];

    int pi = -1, xi = -1;
    for (int i = 0; i < n_in; i++) {
        if (i == zi) continue;
        if ((long long)in_sizes[i] == (long long)D * (long long)D && pi < 0) pi = i;
        else xi = i;
    }
    if (pi < 0 || xi < 0) { xi = 0; pi = 1; }

    const float* x = (const float*)d_in[xi];
    const float* P = (const float*)d_in[pi];
    const float* z = (const float*)d_in[zi];
    float* out = (float*)d_out;

    const int B = in_sizes[xi] / D;

    prep_kernel<<<1, 1024>>>(P, z, D);
    dot_kernel<<<(B + 3) / 4, 128>>>(x, D, B);
    apply_kernel<<<B, 256>>>(x, out, D);
}